// round 2
// baseline (speedup 1.0000x reference)
#include <cuda_runtime.h>
#include <math.h>

// ---------------------------------------------------------------------------
// PoetryGPT forward: B=2, T=1024, D=1024, H=16, HD=64, L=8, V=32000, fp32
// ---------------------------------------------------------------------------
#define D_MODEL 1024
#define NHEAD   16
#define HDIM    64
#define SEQ     1024
#define NLAYER  8
#define BATCH   2
#define BT      (BATCH*SEQ)   // 2048
#define DFF     4096
#define VOCAB   32000

// ---- scratch (static device globals: allocation-guard safe) ----
__device__ float g_h   [(size_t)BT*D_MODEL];            // residual stream
__device__ float g_ln  [(size_t)BT*D_MODEL];            // layernorm output
__device__ float g_qkv [(size_t)BT*3*D_MODEL];          // fused QKV
__device__ float g_o   [(size_t)BT*D_MODEL];            // attention out (head-concat)
__device__ float g_f   [(size_t)BT*DFF];                // MLP hidden
__device__ float g_wqkv[(size_t)NLAYER*D_MODEL*3*D_MODEL]; // repacked QKV weights

// ---------------------------------------------------------------------------
// Repack Wq/Wk/Wv [L,H,D,HD] -> g_wqkv[L][D][3*D]  (col = w*1024 + h*64 + e)
// ---------------------------------------------------------------------------
__global__ void repack_kernel(const float* __restrict__ Wq,
                              const float* __restrict__ Wk,
                              const float* __restrict__ Wv)
{
    size_t i = (size_t)blockIdx.x * 256 + threadIdx.x;
    // i = ((((l*3 + w)*NHEAD + h)*D_MODEL + d)*HDIM + e)
    int e = (int)(i & 63);        size_t r = i >> 6;
    int d = (int)(r & 1023);      r >>= 10;
    int h = (int)(r & 15);        r >>= 4;
    int w = (int)(r % 3);
    int l = (int)(r / 3);
    const float* W = (w == 0) ? Wq : (w == 1) ? Wk : Wv;
    float v = W[(((size_t)l*NHEAD + h)*D_MODEL + d)*HDIM + e];
    g_wqkv[((size_t)l*D_MODEL + d)*(3*D_MODEL) + (size_t)w*D_MODEL + h*HDIM + e] = v;
}

// ---------------------------------------------------------------------------
// h = tok_emb[x] + pos_emb
// ---------------------------------------------------------------------------
__global__ void embed_kernel(const int* __restrict__ x,
                             const float* __restrict__ tok,
                             const float* __restrict__ pos)
{
    int i  = blockIdx.x * 256 + threadIdx.x;   // over BT*D
    int d  = i & (D_MODEL - 1);
    int bt = i >> 10;
    int t  = bt & (SEQ - 1);
    int id = x[bt];
    g_h[i] = tok[(size_t)id * D_MODEL + d] + pos[(size_t)t * D_MODEL + d];
}

// ---------------------------------------------------------------------------
// LayerNorm: one block per row of 1024, 256 threads x float4
// ---------------------------------------------------------------------------
__global__ __launch_bounds__(256)
void ln_kernel(const float* __restrict__ x, const float* __restrict__ gw,
               const float* __restrict__ bw, float* __restrict__ y)
{
    int row = blockIdx.x, tid = threadIdx.x;
    float4 v = ((const float4*)(x + (size_t)row * D_MODEL))[tid];
    float s = v.x + v.y + v.z + v.w;
    float q = v.x*v.x + v.y*v.y + v.z*v.z + v.w*v.w;
    #pragma unroll
    for (int o = 16; o > 0; o >>= 1) {
        s += __shfl_xor_sync(0xffffffffu, s, o);
        q += __shfl_xor_sync(0xffffffffu, q, o);
    }
    __shared__ float ssum[8], ssq[8];
    if ((tid & 31) == 0) { ssum[tid >> 5] = s; ssq[tid >> 5] = q; }
    __syncthreads();
    float ts = 0.f, tq = 0.f;
    #pragma unroll
    for (int i = 0; i < 8; i++) { ts += ssum[i]; tq += ssq[i]; }
    float mu   = ts * (1.f / D_MODEL);
    float var  = tq * (1.f / D_MODEL) - mu * mu;
    float rstd = rsqrtf(var + 1e-5f);
    float4 g4 = ((const float4*)gw)[tid];
    float4 b4 = ((const float4*)bw)[tid];
    float4 o4;
    o4.x = (v.x - mu) * rstd * g4.x + b4.x;
    o4.y = (v.y - mu) * rstd * g4.y + b4.y;
    o4.z = (v.z - mu) * rstd * g4.z + b4.z;
    o4.w = (v.w - mu) * rstd * g4.w + b4.w;
    ((float4*)(y + (size_t)row * D_MODEL))[tid] = o4;
}

// ---------------------------------------------------------------------------
// Generic SGEMM: C[M,N] = (RES? res : 0) + A[M,K]*B[K,N] + (BIAS? bias : 0)
// 128x128 tile, BK=8, 256 threads, 8x8 per thread.
// Requires: M%128==0, N%128==0, K%8==0 (true for all shapes here).
// ---------------------------------------------------------------------------
#define BM 128
#define BN 128
#define BK 8
#define TM 8
#define TN 8

template <bool BIAS, bool RELU, bool RES>
__global__ __launch_bounds__(256)
void sgemm(const float* __restrict__ A, const float* __restrict__ B,
           const float* __restrict__ bias, const float* __restrict__ res,
           float* __restrict__ C, int M, int N, int K)
{
    __shared__ float As[BK][BM];
    __shared__ float Bs[BK][BN];

    int tid = threadIdx.x;
    int tx  = tid & 15;        // 0..15 (cols)
    int ty  = tid >> 4;        // 0..15 (rows)
    int row0 = blockIdx.y * BM;
    int col0 = blockIdx.x * BN;

    int aRow  = tid >> 1;          // 0..127
    int aCol4 = (tid & 1) * 4;     // 0 or 4
    int bRow  = tid >> 5;          // 0..7
    int bCol4 = (tid & 31) * 4;    // 0..124

    const float* Aptr = A + (size_t)(row0 + aRow) * K + aCol4;
    const float* Bptr = B + (size_t)bRow * N + col0 + bCol4;

    float acc[TM][TN] = {};

    for (int k0 = 0; k0 < K; k0 += BK) {
        float4 av = *(const float4*)Aptr;
        float4 bv = *(const float4*)Bptr;
        Aptr += BK;
        Bptr += (size_t)BK * N;

        As[aCol4 + 0][aRow] = av.x;
        As[aCol4 + 1][aRow] = av.y;
        As[aCol4 + 2][aRow] = av.z;
        As[aCol4 + 3][aRow] = av.w;
        *(float4*)&Bs[bRow][bCol4] = bv;
        __syncthreads();

        #pragma unroll
        for (int kk = 0; kk < BK; kk++) {
            float4 a0 = *(const float4*)&As[kk][ty * TM];
            float4 a1 = *(const float4*)&As[kk][ty * TM + 4];
            float4 b0 = *(const float4*)&Bs[kk][tx * TN];
            float4 b1 = *(const float4*)&Bs[kk][tx * TN + 4];
            float ar[TM] = {a0.x, a0.y, a0.z, a0.w, a1.x, a1.y, a1.z, a1.w};
            float br[TN] = {b0.x, b0.y, b0.z, b0.w, b1.x, b1.y, b1.z, b1.w};
            #pragma unroll
            for (int i = 0; i < TM; i++)
                #pragma unroll
                for (int j = 0; j < TN; j++)
                    acc[i][j] += ar[i] * br[j];
        }
        __syncthreads();
    }

    #pragma unroll
    for (int i = 0; i < TM; i++) {
        size_t r = (size_t)(row0 + ty * TM + i);
        float*       Crow = C   + r * N;
        const float* Rrow = RES ? res + r * N : nullptr;
        #pragma unroll
        for (int j = 0; j < TN; j++) {
            int c = col0 + tx * TN + j;
            float v = acc[i][j];
            if (BIAS) v += bias[c];
            if (RES)  v += Rrow[c];
            if (RELU) v = fmaxf(v, 0.f);
            Crow[c] = v;
        }
    }
}

// ---------------------------------------------------------------------------
// Causal attention, one block per (query row, b*h). 128 threads.
// qkv layout: row bt = b*SEQ+t, cols [0,1024)=Q, [1024,2048)=K, [2048,3072)=V,
// head h occupies cols h*64..h*64+63 of each third.
// scale = 1/sqrt(D_MODEL) = 1/32 (reference uses emb_dim scaling).
// ---------------------------------------------------------------------------
__global__ __launch_bounds__(128)
void attn_kernel()
{
    int tq = blockIdx.x;
    int bh = blockIdx.y;
    int b  = bh >> 4;
    int h  = bh & 15;
    int tid = threadIdx.x;

    __shared__ float sq[HDIM];
    __shared__ float sc[SEQ];
    __shared__ float red[128];

    const float* qrow  = g_qkv + ((size_t)(b*SEQ + tq)) * (3*D_MODEL) + h*HDIM;
    const float* kbase = g_qkv + (size_t)b*SEQ*(3*D_MODEL) + D_MODEL   + h*HDIM;
    const float* vbase = g_qkv + (size_t)b*SEQ*(3*D_MODEL) + 2*D_MODEL + h*HDIM;

    if (tid < HDIM) sq[tid] = qrow[tid];
    __syncthreads();

    const float scale = 0.03125f;  // 1/sqrt(1024)
    float lmax = -3.4e38f;
    for (int s = tid; s <= tq; s += 128) {
        const float4* k4 = (const float4*)(kbase + (size_t)s * (3*D_MODEL));
        const float4* q4 = (const float4*)sq;
        float acc = 0.f;
        #pragma unroll
        for (int i = 0; i < HDIM/4; i++) {
            float4 kv = k4[i], qv = q4[i];
            acc += kv.x*qv.x + kv.y*qv.y + kv.z*qv.z + kv.w*qv.w;
        }
        acc *= scale;
        sc[s] = acc;
        lmax = fmaxf(lmax, acc);
    }

    // block max
    red[tid] = lmax; __syncthreads();
    for (int st = 64; st > 0; st >>= 1) {
        if (tid < st) red[tid] = fmaxf(red[tid], red[tid + st]);
        __syncthreads();
    }
    float m = red[0];
    __syncthreads();

    // exp + block sum
    float lsum = 0.f;
    for (int s = tid; s <= tq; s += 128) {
        float p = __expf(sc[s] - m);
        sc[s] = p;
        lsum += p;
    }
    red[tid] = lsum; __syncthreads();
    for (int st = 64; st > 0; st >>= 1) {
        if (tid < st) red[tid] += red[tid + st];
        __syncthreads();
    }
    float inv = 1.f / red[0];
    __syncthreads();

    // O = P * V  (2 threads per output dim, split over even/odd s)
    int e = tid & 63, half = tid >> 6;
    float acc = 0.f;
    for (int s = half; s <= tq; s += 2)
        acc += sc[s] * vbase[(size_t)s * (3*D_MODEL) + e];
    red[tid] = acc; __syncthreads();
    if (tid < HDIM)
        g_o[((size_t)(b*SEQ + tq)) * D_MODEL + h*HDIM + e] =
            (red[tid] + red[tid + 64]) * inv;
}

// ---------------------------------------------------------------------------
// Launch
// ---------------------------------------------------------------------------
static inline dim3 ggrid(int M, int N) { return dim3(N / BN, M / BM); }

extern "C" void kernel_launch(void* const* d_in, const int* in_sizes, int n_in,
                              void* d_out, int out_size)
{
    const int*   x      = (const int*)  d_in[0];
    const float* tok    = (const float*)d_in[1];
    const float* pos    = (const float*)d_in[2];
    const float* Wq     = (const float*)d_in[3];
    const float* Wk     = (const float*)d_in[4];
    const float* Wv     = (const float*)d_in[5];
    const float* Wproj  = (const float*)d_in[6];
    const float* bproj  = (const float*)d_in[7];
    const float* ln1_g  = (const float*)d_in[8];
    const float* ln1_b  = (const float*)d_in[9];
    const float* ln2_g  = (const float*)d_in[10];
    const float* ln2_b  = (const float*)d_in[11];
    const float* W1     = (const float*)d_in[12];
    const float* b1     = (const float*)d_in[13];
    const float* W2     = (const float*)d_in[14];
    const float* b2     = (const float*)d_in[15];
    const float* lnf_g  = (const float*)d_in[16];
    const float* lnf_b  = (const float*)d_in[17];
    const float* Wlm    = (const float*)d_in[18];
    const float* blm    = (const float*)d_in[19];
    float* out = (float*)d_out;

    float *h_, *ln_, *qkv_, *o_, *f_, *wq_;
    cudaGetSymbolAddress((void**)&h_,   g_h);
    cudaGetSymbolAddress((void**)&ln_,  g_ln);
    cudaGetSymbolAddress((void**)&qkv_, g_qkv);
    cudaGetSymbolAddress((void**)&o_,   g_o);
    cudaGetSymbolAddress((void**)&f_,   g_f);
    cudaGetSymbolAddress((void**)&wq_,  g_wqkv);

    // repack QKV weights: 8*3*16*1024*64 = 25,165,824 elems
    {
        size_t n = (size_t)NLAYER * 3 * NHEAD * D_MODEL * HDIM;
        repack_kernel<<<(unsigned)(n / 256), 256>>>(Wq, Wk, Wv);
    }

    // embeddings
    embed_kernel<<<(BT * D_MODEL) / 256, 256>>>(x, tok, pos);

    for (int l = 0; l < NLAYER; l++) {
        // a_in = LN1(h)
        ln_kernel<<<BT, 256>>>(h_, ln1_g + (size_t)l*D_MODEL, ln1_b + (size_t)l*D_MODEL, ln_);
        // qkv = a_in @ Wqkv_packed
        sgemm<false, false, false><<<ggrid(BT, 3*D_MODEL), 256>>>(
            ln_, wq_ + (size_t)l*D_MODEL*3*D_MODEL, nullptr, nullptr, qkv_,
            BT, 3*D_MODEL, D_MODEL);
        // attention
        attn_kernel<<<dim3(SEQ, BATCH*NHEAD), 128>>>();
        // h = h + o @ Wproj + bproj
        sgemm<true, false, true><<<ggrid(BT, D_MODEL), 256>>>(
            o_, Wproj + (size_t)l*D_MODEL*D_MODEL, bproj + (size_t)l*D_MODEL, h_, h_,
            BT, D_MODEL, D_MODEL);
        // f_in = LN2(h)
        ln_kernel<<<BT, 256>>>(h_, ln2_g + (size_t)l*D_MODEL, ln2_b + (size_t)l*D_MODEL, ln_);
        // f = relu(f_in @ W1 + b1)
        sgemm<true, true, false><<<ggrid(BT, DFF), 256>>>(
            ln_, W1 + (size_t)l*D_MODEL*DFF, b1 + (size_t)l*DFF, nullptr, f_,
            BT, DFF, D_MODEL);
        // h = h + f @ W2 + b2
        sgemm<true, false, true><<<ggrid(BT, D_MODEL), 256>>>(
            f_, W2 + (size_t)l*DFF*D_MODEL, b2 + (size_t)l*D_MODEL, h_, h_,
            BT, D_MODEL, DFF);
    }

    // final LN + LM head
    ln_kernel<<<BT, 256>>>(h_, lnf_g, lnf_b, ln_);
    sgemm<true, false, false><<<ggrid(BT, VOCAB), 256>>>(
        ln_, Wlm, blm, nullptr, out, BT, VOCAB, D_MODEL);
}